// round 10
// baseline (speedup 1.0000x reference)
#include <cuda_runtime.h>

#define C 100
#define DCUT 8   // CODE(d>=8) < 5e-15: invisible in float outputs

// ===========================================================================
// Compile-time target table: T[mu][j] = softmax_j( pdf(j; mu) ),
// tlogt[mu] = sum_j T*log(T). Underflow-safe constexpr double math,
// statically initialized into device memory -> zero runtime init cost.
// ===========================================================================
struct alignas(16) Tab {
    float T[C * C];
    float tlogt[C];
};

constexpr double cexp_t(double x) {   // 0 <= x <= 0.5, underflow-safe
    if (x < 1e-8) return 1.0 + x + 0.5 * x * x;
    double term = 1.0, sum = 1.0;
    for (int i = 1; i <= 20; ++i) {
        term *= x / (double)i;
        sum += term;
        if (term < 1e-20 * sum) break;   // stop before terms can underflow
    }
    return sum;
}
constexpr double cpowi(double b, int e) {  // no trailing square -> no underflow
    double r = 1.0;
    while (e) { if (e & 1) r *= b; e >>= 1; if (e) b *= b; }
    return r;
}
constexpr double cln1p(double u) {    // |u| <= 0.05, atanh series
    double y = u / (2.0 + u);
    double y2 = y * y, term = y, sum = y;
    for (int i = 1; i <= 10; ++i) { term *= y2; sum += term / (double)(2 * i + 1); }
    return 2.0 * sum;
}

constexpr Tab make_tab() {
    Tab t{};
    const double LN100    = 4.60517018598809136803598290936873;
    const double INV_NORM = 0.39894228040143267793994605993438;  // 1/sqrt(2pi)

    // distance-indexed caches; beyond DCUT the pdf is < 5e-15 -> treat as 0
    double CODE[C] = {};   // INV_NORM * exp(-0.5*d^2)
    double EX[C]   = {};   // exp(CODE[d])
    const double p = cexp_t(0.5);          // e^{+1/2}; use reciprocal powers
    for (int d = 0; d < C; ++d) {
        if (d < DCUT) {                    // max exponent 49 -> p^49 ~ e^24.5, safe
            CODE[d] = INV_NORM / cpowi(p, d * d);
            EX[d]   = cexp_t(CODE[d]);
        } else {
            CODE[d] = 0.0;
            EX[d]   = 1.0;
        }
    }

    for (int mu = 0; mu < C; ++mu) {
        double Z = 0.0;
        for (int j = 0; j < C; ++j) {
            int d = j - mu; if (d < 0) d = -d;
            Z += EX[d];
        }
        const double lnZ = LN100 + cln1p((Z - 100.0) * 0.01);  // Z in [100,101.5]
        double tl = 0.0;
        for (int j = 0; j < C; ++j) {
            int d = j - mu; if (d < 0) d = -d;
            double tv = EX[d] / Z;
            t.T[mu * C + j] = (float)tv;
            tl += tv * (CODE[d] - lnZ);    // t * log t, exact
        }
        t.tlogt[mu] = (float)tl;
    }
    return t;
}

__device__ constexpr Tab g_tab = make_tab();   // compile-time init, no kernel

__device__ double       g_accum;   // zero-init; winner resets each run
__device__ unsigned int g_count;   // ditto

// ===========================================================================
// Single fused kernel: grid-stride warp-per-row, 2-way unrolled.
// Per row only sum(exp) needs warp shuffles; the target dot is linear ->
// per-lane deferred accumulation, reduced once per warp. One double atomic
// per block (1184 total); last block finalizes output and resets globals.
// ===========================================================================
__global__ void __launch_bounds__(256, 8)
LossLD_kernel(const float* __restrict__ scores,
              const int* __restrict__ labels,
              float* __restrict__ out,
              int rows) {
    const int lane = threadIdx.x & 31;
    const int wib  = threadIdx.x >> 5;
    const int gw   = (int)((blockIdx.x * blockDim.x + threadIdx.x) >> 5);
    const int W    = (int)((gridDim.x * blockDim.x) >> 5);   // total warps

    const bool act = (lane < 25);
    const float4* __restrict__ sp = (const float4*)scores;
    const float4* __restrict__ tp = (const float4*)g_tab.T;

    float dotacc = 0.f;   // per-lane, reduced once at the end
    float scal   = 0.f;   // lane0: sum of (tlogt[mu] + log(sum exp))

    int r = gw;
    for (; r + W < rows; r += 2 * W) {
        const int ra = r, rb = r + W;
        int mua = __ldg(labels + ra);
        int mub = __ldg(labels + rb);
        mua = min(max(mua, 0), C - 1);
        mub = min(max(mub, 0), C - 1);

        float sea = 0.f, seb = 0.f;
        if (act) {
            float4 sa = __ldg(sp + (size_t)ra * 25 + lane);
            float4 sb = __ldg(sp + (size_t)rb * 25 + lane);
            float4 ta = __ldg(tp + mua * 25 + lane);
            float4 tb = __ldg(tp + mub * 25 + lane);
            sea = __expf(sa.x) + __expf(sa.y) + __expf(sa.z) + __expf(sa.w);
            seb = __expf(sb.x) + __expf(sb.y) + __expf(sb.z) + __expf(sb.w);
            dotacc = fmaf(ta.x, sa.x, fmaf(ta.y, sa.y,
                     fmaf(ta.z, sa.z, fmaf(ta.w, sa.w, dotacc))));
            dotacc = fmaf(tb.x, sb.x, fmaf(tb.y, sb.y,
                     fmaf(tb.z, sb.z, fmaf(tb.w, sb.w, dotacc))));
        }
        #pragma unroll
        for (int o = 16; o; o >>= 1) {
            sea += __shfl_xor_sync(0xffffffffu, sea, o);
            seb += __shfl_xor_sync(0xffffffffu, seb, o);
        }
        if (lane == 0)   // log(a)+log(b) = log(a*b): sums ~165, product safe
            scal += g_tab.tlogt[mua] + g_tab.tlogt[mub] + __logf(sea * seb);
    }
    while (r < rows) {   // remainder rows
        int mu = __ldg(labels + r);
        mu = min(max(mu, 0), C - 1);
        float se = 0.f;
        if (act) {
            float4 s = __ldg(sp + (size_t)r * 25 + lane);
            float4 t = __ldg(tp + mu * 25 + lane);
            se = __expf(s.x) + __expf(s.y) + __expf(s.z) + __expf(s.w);
            dotacc = fmaf(t.x, s.x, fmaf(t.y, s.y,
                     fmaf(t.z, s.z, fmaf(t.w, s.w, dotacc))));
        }
        #pragma unroll
        for (int o = 16; o; o >>= 1) se += __shfl_xor_sync(0xffffffffu, se, o);
        if (lane == 0) scal += g_tab.tlogt[mu] + __logf(se);
        r += W;
    }

    // one-time dot reduction per warp
    #pragma unroll
    for (int o = 16; o; o >>= 1) dotacc += __shfl_xor_sync(0xffffffffu, dotacc, o);

    __shared__ float wsum[8];
    if (lane == 0) wsum[wib] = scal - dotacc;
    __syncthreads();
    if (threadIdx.x == 0) {
        float bs = wsum[0] + wsum[1] + wsum[2] + wsum[3]
                 + wsum[4] + wsum[5] + wsum[6] + wsum[7];
        atomicAdd(&g_accum, (double)bs);
        __threadfence();
        unsigned int ticket = atomicAdd(&g_count, 1u);
        if (ticket == gridDim.x - 1) {           // last block: finalize + reset
            double total = *(volatile double*)&g_accum;
            out[0] = (float)(total / (double)rows);
            *(volatile double*)&g_accum = 0.0;   // deterministic across replays
            *(volatile unsigned int*)&g_count = 0u;
        }
    }
}

// ---------------------------------------------------------------------------
// inputs: [0] scores float32 (n*c), [1] labels int32 (n) ; output: scalar f32
// ---------------------------------------------------------------------------
extern "C" void kernel_launch(void* const* d_in, const int* in_sizes, int n_in,
                              void* d_out, int out_size) {
    const float* scores = (const float*)d_in[0];
    const int*   labels = (const int*)d_in[1];
    float*       out    = (float*)d_out;

    const int rows = in_sizes[1];   // 262144
    int blocks = 148 * 8;           // exactly one wave at 8 blocks/SM
    if (blocks * 8 > rows) blocks = (rows + 7) / 8;

    LossLD_kernel<<<blocks, 256>>>(scores, labels, out, rows);
}

// round 12
// speedup vs baseline: 1.2864x; 1.2864x over previous
#include <cuda_runtime.h>

#define C 100
#define DCUT 8   // pdf(d>=8) < 5e-15: invisible in float outputs

// ===========================================================================
// Compile-time scalars: EX[d]=exp(code(d)) for d<8, invZ[mu], tlogt[mu].
// Tiny arrays (const bank). The full 100x100 table is rebuilt per-block in
// SHARED memory from these (40KB smem), so hot-loop reads are LDS.128, and
// the only global traffic is the scores tensor.
// ===========================================================================
struct Small {
    float ex[DCUT];     // exp(code(d)),  code(d) = invnorm*exp(-d^2/2)
    float invZ[C];      // 1 / sum_j exp(code(|j-mu|))
    float tlogt[C];     // sum_j T*log(T)
};

constexpr double cexp_t(double x) {   // 0 <= x <= 0.5, underflow-safe
    if (x < 1e-8) return 1.0 + x + 0.5 * x * x;
    double term = 1.0, sum = 1.0;
    for (int i = 1; i <= 20; ++i) {
        term *= x / (double)i;
        sum += term;
        if (term < 1e-20 * sum) break;
    }
    return sum;
}
constexpr double cpowi(double b, int e) {
    double r = 1.0;
    while (e) { if (e & 1) r *= b; e >>= 1; if (e) b *= b; }
    return r;
}
constexpr double cln1p(double u) {    // |u| <= 0.05
    double y = u / (2.0 + u);
    double y2 = y * y, term = y, sum = y;
    for (int i = 1; i <= 10; ++i) { term *= y2; sum += term / (double)(2 * i + 1); }
    return 2.0 * sum;
}

constexpr Small make_small() {
    Small s{};
    const double LN100    = 4.60517018598809136803598290936873;
    const double INV_NORM = 0.39894228040143267793994605993438;  // 1/sqrt(2pi)

    double CODE[C] = {}, EX[C] = {};
    const double p = cexp_t(0.5);              // e^{1/2}
    for (int d = 0; d < C; ++d) {
        if (d < DCUT) {
            CODE[d] = INV_NORM / cpowi(p, d * d);   // invnorm * e^{-d^2/2}
            EX[d]   = cexp_t(CODE[d]);
            s.ex[d] = (float)EX[d];
        } else { CODE[d] = 0.0; EX[d] = 1.0; }
    }
    for (int mu = 0; mu < C; ++mu) {
        double Z = 0.0;
        for (int j = 0; j < C; ++j) {
            int d = j - mu; if (d < 0) d = -d;
            Z += EX[d];
        }
        s.invZ[mu] = (float)(1.0 / Z);
        const double lnZ = LN100 + cln1p((Z - 100.0) * 0.01);   // Z in [100,101.5]
        double tl = 0.0;
        for (int j = 0; j < C; ++j) {
            int d = j - mu; if (d < 0) d = -d;
            tl += (EX[d] / Z) * (CODE[d] - lnZ);    // t * log t
        }
        s.tlogt[mu] = (float)tl;
    }
    return s;
}

__device__ constexpr Small g_sm = make_small();   // const bank: small + mostly uniform access

__device__ double       g_accum;   // zero-init; winner resets each run
__device__ unsigned int g_count;   // ditto

// ===========================================================================
// One fused kernel. Per-block: build the 100x100 target table in SMEM
// (2500 float4), then grid-stride warp-per-row, 2-way unrolled:
//   scores: LDG.128 (only global traffic) ; table row: LDS.128 ;
//   sum(exp) warp-reduced per row; target dot deferred per-lane;
//   one double atomic per block; last block finalizes + resets.
// ===========================================================================
__global__ void __launch_bounds__(256, 5)
LossLD_kernel(const float* __restrict__ scores,
              const int* __restrict__ labels,
              float* __restrict__ out,
              int rows) {
    __shared__ float4 sT[C * 25];      // 40000B: T[mu][j], row = 25 float4
    __shared__ float  wsum[8];

    const int lane = threadIdx.x & 31;
    const int wib  = threadIdx.x >> 5;

    // ---- build normalized table in smem from constexpr constants ----
    for (int f = threadIdx.x; f < C * 25; f += 256) {
        const int mu = f / 25;
        const int j0 = (f - mu * 25) * 4;
        const float iz = g_sm.invZ[mu];
        float4 v;
        {
            int d = j0 - mu;     if (d < 0) d = -d;
            v.x = (d < DCUT ? g_sm.ex[d] : 1.0f) * iz;
        }
        {
            int d = j0 + 1 - mu; if (d < 0) d = -d;
            v.y = (d < DCUT ? g_sm.ex[d] : 1.0f) * iz;
        }
        {
            int d = j0 + 2 - mu; if (d < 0) d = -d;
            v.z = (d < DCUT ? g_sm.ex[d] : 1.0f) * iz;
        }
        {
            int d = j0 + 3 - mu; if (d < 0) d = -d;
            v.w = (d < DCUT ? g_sm.ex[d] : 1.0f) * iz;
        }
        sT[f] = v;
    }
    __syncthreads();

    const int gw = (int)((blockIdx.x * blockDim.x + threadIdx.x) >> 5);
    const int W  = (int)((gridDim.x * blockDim.x) >> 5);   // total warps

    const bool act = (lane < 25);
    const float4* __restrict__ sp = (const float4*)scores;

    float dotacc = 0.f;   // per-lane, reduced once at the end
    float scal   = 0.f;   // lane0: sum of (tlogt[mu] + log(sum exp))

    int r = gw;
    for (; r + W < rows; r += 2 * W) {
        const int ra = r, rb = r + W;
        int mua = __ldg(labels + ra);
        int mub = __ldg(labels + rb);
        mua = min(max(mua, 0), C - 1);
        mub = min(max(mub, 0), C - 1);

        float sea = 0.f, seb = 0.f;
        if (act) {
            float4 sa = __ldg(sp + (size_t)ra * 25 + lane);
            float4 sb = __ldg(sp + (size_t)rb * 25 + lane);
            float4 ta = sT[mua * 25 + lane];
            float4 tb = sT[mub * 25 + lane];
            sea = __expf(sa.x) + __expf(sa.y) + __expf(sa.z) + __expf(sa.w);
            seb = __expf(sb.x) + __expf(sb.y) + __expf(sb.z) + __expf(sb.w);
            dotacc = fmaf(ta.x, sa.x, fmaf(ta.y, sa.y,
                     fmaf(ta.z, sa.z, fmaf(ta.w, sa.w, dotacc))));
            dotacc = fmaf(tb.x, sb.x, fmaf(tb.y, sb.y,
                     fmaf(tb.z, sb.z, fmaf(tb.w, sb.w, dotacc))));
        }
        #pragma unroll
        for (int o = 16; o; o >>= 1) {
            sea += __shfl_xor_sync(0xffffffffu, sea, o);
            seb += __shfl_xor_sync(0xffffffffu, seb, o);
        }
        if (lane == 0)   // log a + log b = log(a*b): sums ~165 each, safe
            scal += g_sm.tlogt[mua] + g_sm.tlogt[mub] + __logf(sea * seb);
    }
    while (r < rows) {   // remainder rows
        int mu = __ldg(labels + r);
        mu = min(max(mu, 0), C - 1);
        float se = 0.f;
        if (act) {
            float4 s = __ldg(sp + (size_t)r * 25 + lane);
            float4 t = sT[mu * 25 + lane];
            se = __expf(s.x) + __expf(s.y) + __expf(s.z) + __expf(s.w);
            dotacc = fmaf(t.x, s.x, fmaf(t.y, s.y,
                     fmaf(t.z, s.z, fmaf(t.w, s.w, dotacc))));
        }
        #pragma unroll
        for (int o = 16; o; o >>= 1) se += __shfl_xor_sync(0xffffffffu, se, o);
        if (lane == 0) scal += g_sm.tlogt[mu] + __logf(se);
        r += W;
    }

    // one-time dot reduction per warp
    #pragma unroll
    for (int o = 16; o; o >>= 1) dotacc += __shfl_xor_sync(0xffffffffu, dotacc, o);

    if (lane == 0) wsum[wib] = scal - dotacc;
    __syncthreads();
    if (threadIdx.x == 0) {
        float bs = wsum[0] + wsum[1] + wsum[2] + wsum[3]
                 + wsum[4] + wsum[5] + wsum[6] + wsum[7];
        atomicAdd(&g_accum, (double)bs);
        __threadfence();
        unsigned int ticket = atomicAdd(&g_count, 1u);
        if (ticket == gridDim.x - 1) {           // last block: finalize + reset
            double total = *(volatile double*)&g_accum;
            out[0] = (float)(total / (double)rows);
            *(volatile double*)&g_accum = 0.0;   // deterministic across replays
            *(volatile unsigned int*)&g_count = 0u;
        }
    }
}

// ---------------------------------------------------------------------------
// inputs: [0] scores float32 (n*c), [1] labels int32 (n) ; output: scalar f32
// ---------------------------------------------------------------------------
extern "C" void kernel_launch(void* const* d_in, const int* in_sizes, int n_in,
                              void* d_out, int out_size) {
    const float* scores = (const float*)d_in[0];
    const int*   labels = (const int*)d_in[1];
    float*       out    = (float*)d_out;

    const int rows = in_sizes[1];   // 262144
    int blocks = 148 * 5;           // one wave at 5 blocks/SM (40KB smem each)
    if (blocks * 8 > rows) blocks = (rows + 7) / 8;

    LossLD_kernel<<<blocks, 256>>>(scores, labels, out, rows);
}